// round 13
// baseline (speedup 1.0000x reference)
#include <cuda_runtime.h>
#include <math.h>

#define TABLE_SIZE 4194304          // 2^22
#define TABLE_MASK (TABLE_SIZE - 1)
#define NVOX (128*128*128)          // 2,097,152
#define NB 1024                     // global buckets (idx >> 12)
#define BSHIFT 12
#define NBLK 512                    // hist/scatter fat blocks
#define CHUNK (NVOX / NBLK)         // 4096
#define RB 512                      // reduce blocks inside fused kernel
#define SUBNB 4096                  // in-block sort bins (idx & 4095)
#define CAP 2816                    // max records locally sorted per bucket
#define MYMAX 6                     // ceil(CAP/512) records per thread

// ---------------- device-global scratch (allocation-free) ----------------
__device__ double   g_part_s[RB];
__device__ double   g_part_ss[RB];
__device__ float    g_mean;
__device__ float    g_inv_std;
__device__ unsigned g_bhist[NBLK * NB];   // 2 MB
__device__ unsigned g_base[NB];
__device__ uint2    g_records[NVOX];      // (voxel_id, packed coords) 16 MB

__device__ __forceinline__ unsigned hash_idx(int cx, int cy, int cz) {
    unsigned h = (unsigned)cx ^ ((unsigned)cy * 2654435761u)
                             ^ ((unsigned)cz * 805459861u);
    return h & TABLE_MASK;
}
__device__ __forceinline__ unsigned hash_pc(unsigned pc) {
    return hash_idx((int)(pc & 127u), (int)((pc >> 7) & 127u),
                    (int)((pc >> 14) & 127u));
}

// ------- stage 1 (fused): table stats reduce + coord bucket histograms -------
__global__ void __launch_bounds__(1024)
reduce_hist_kernel(const float4* __restrict__ p, const int* __restrict__ coords)
{
    if (blockIdx.x < RB) {
        const int M4 = 3 * TABLE_SIZE / 4;
        double s = 0.0, ss = 0.0;
        int stride = RB * 1024;
        for (int i = blockIdx.x * 1024 + threadIdx.x; i < M4; i += stride) {
            float4 v = __ldcs(p + i);
            s  += (double)v.x + (double)v.y + (double)v.z + (double)v.w;
            ss += (double)v.x * v.x + (double)v.y * v.y
                + (double)v.z * v.z + (double)v.w * v.w;
        }
        #pragma unroll
        for (int o = 16; o > 0; o >>= 1) {
            s  += __shfl_down_sync(0xffffffffu, s,  o);
            ss += __shfl_down_sync(0xffffffffu, ss, o);
        }
        __shared__ double sh_s[32], sh_ss[32];
        int w = threadIdx.x >> 5, l = threadIdx.x & 31;
        if (l == 0) { sh_s[w] = s; sh_ss[w] = ss; }
        __syncthreads();
        if (threadIdx.x == 0) {
            double ts = 0.0, tss = 0.0;
            for (int k = 0; k < 32; k++) { ts += sh_s[k]; tss += sh_ss[k]; }
            g_part_s[blockIdx.x]  = ts;
            g_part_ss[blockIdx.x] = tss;
        }
    } else {
        __shared__ unsigned sh[NB];
        sh[threadIdx.x] = 0u;
        __syncthreads();
        int b = blockIdx.x - RB;
        int base = b * CHUNK;
        #pragma unroll 4
        for (int v = threadIdx.x; v < CHUNK; v += 1024) {
            int i = base + v;
            unsigned idx = hash_idx(coords[3*i], coords[3*i+1], coords[3*i+2]);
            atomicAdd(&sh[idx >> BSHIFT], 1u);
        }
        __syncthreads();
        g_bhist[(size_t)b * NB + threadIdx.x] = sh[threadIdx.x];
    }
}

// ---- stage 2: per-(block,bucket) exclusive offsets + stats finalize (fused) ----
__global__ void __launch_bounds__(NB)
offsets_kernel() {
    int k = threadIdx.x;
    {
        double s  = (k < RB) ? g_part_s[k]  : 0.0;
        double ss = (k < RB) ? g_part_ss[k] : 0.0;
        #pragma unroll
        for (int o = 16; o > 0; o >>= 1) {
            s  += __shfl_down_sync(0xffffffffu, s,  o);
            ss += __shfl_down_sync(0xffffffffu, ss, o);
        }
        __shared__ double sh_s[32], sh_ss[32];
        int w = k >> 5, l = k & 31;
        if (l == 0) { sh_s[w] = s; sh_ss[w] = ss; }
        __syncthreads();
        if (k == 0) {
            double ts = 0.0, tss = 0.0;
            for (int q = 0; q < 32; q++) { ts += sh_s[q]; tss += sh_ss[q]; }
            const double M = 3.0 * (double)TABLE_SIZE;
            double mean = ts / M;
            double var  = (tss - ts * ts / M) / (M - 1.0);
            g_mean    = (float)mean;
            g_inv_std = (float)(1.0 / sqrt(var));
        }
        __syncthreads();
    }

    unsigned run = 0;
    #pragma unroll 8
    for (int b = 0; b < NBLK; b++) {
        unsigned t = g_bhist[(size_t)b * NB + k];
        g_bhist[(size_t)b * NB + k] = run;
        run += t;
    }
    __shared__ unsigned s[NB];
    s[k] = run;
    __syncthreads();
    for (int off = 1; off < NB; off <<= 1) {
        unsigned v = (k >= off) ? s[k - off] : 0u;
        __syncthreads();
        s[k] += v;
        __syncthreads();
    }
    g_base[k] = s[k] - run;
}

// ------- stage 3: scatter v2 — smem counting-sort, near-coalesced writes -------
__global__ void __launch_bounds__(1024)
scatter_kernel(const int* __restrict__ coords) {
    __shared__ unsigned cur[NB];      // global dest base per bucket (this block)
    __shared__ unsigned lcnt[NB];     // local counts -> running cursors
    __shared__ unsigned lbase[NB];    // local exclusive bases
    __shared__ uint2    srec[CHUNK];  // 32 KB block-sorted records

    int b = blockIdx.x;
    int k = threadIdx.x;
    cur[k]  = g_base[k] + g_bhist[(size_t)b * NB + k];
    lcnt[k] = 0u;
    __syncthreads();

    int base = b * CHUNK;
    unsigned my_i[4], my_pc[4], my_bk[4];
    #pragma unroll
    for (int q = 0; q < 4; q++) {
        int i = base + k + (q << 10);
        int cx = __ldcs(coords + 3*i + 0);
        int cy = __ldcs(coords + 3*i + 1);
        int cz = __ldcs(coords + 3*i + 2);
        unsigned idx = hash_idx(cx, cy, cz);
        my_i[q]  = (unsigned)i;
        my_pc[q] = (unsigned)cx | ((unsigned)cy << 7) | ((unsigned)cz << 14);
        my_bk[q] = idx >> BSHIFT;
        atomicAdd(&lcnt[my_bk[q]], 1u);
    }
    __syncthreads();

    // exclusive scan of lcnt (1024 bins) via Hillis-Steele in lbase
    unsigned own = lcnt[k];
    lbase[k] = own;
    __syncthreads();
    for (int off = 1; off < NB; off <<= 1) {
        unsigned v = (k >= off) ? lbase[k - off] : 0u;
        __syncthreads();
        lbase[k] += v;
        __syncthreads();
    }
    unsigned excl = lbase[k] - own;
    __syncthreads();
    lbase[k] = excl;
    lcnt[k]  = excl;
    __syncthreads();

    // local scatter into bucket-sorted smem order
    #pragma unroll
    for (int q = 0; q < 4; q++) {
        unsigned pos = atomicAdd(&lcnt[my_bk[q]], 1u);
        srec[pos] = make_uint2(my_i[q], my_pc[q]);
    }
    __syncthreads();

    // write out in sorted order: bucket runs -> consecutive destinations
    #pragma unroll
    for (int q = 0; q < 4; q++) {
        int p = k + (q << 10);
        uint2 r = srec[p];
        unsigned bk = hash_pc(r.y) >> BSHIFT;
        unsigned dest = cur[bk] + ((unsigned)p - lbase[bk]);
        g_records[dest] = r;
    }
}

// ---------------- stage 4: per-bucket local sort (perm) + process (R10) ---------
__device__ __forceinline__ float fsigmoid(float x) {
    return 1.0f / (1.0f + __expf(-x));
}

__device__ __forceinline__ void
compute_rec(uint2 r, const float* __restrict__ ht,
            float scale_fac, float far, float c0, float c1, float c2,
            float mean, float kfac,
            float4& o0, float4& o1, float4& o2, float4& o3, unsigned& iout)
{
    iout = r.x;
    unsigned pc = r.y;
    unsigned idx = hash_pc(pc);

    float f[14];
    #pragma unroll
    for (int q = 0; q < 14; q++)
        f[q] = __ldg(ht + (size_t)q * TABLE_SIZE + idx);

    int cx = (int)( pc        & 127u);
    int cy = (int)((pc >> 7)  & 127u);
    int cz = (int)((pc >> 14) & 127u);

    float d0 = (f[0] - mean) * kfac;
    float d1 = (f[1] - mean) * kfac;
    float d2 = (f[2] - mean) * kfac;

    float off = 0.5f * scale_fac - far;
    float m0 = d0 + (float)cx * scale_fac + off + c0;
    float m1 = d1 + (float)cy * scale_fac + off + c1;
    float m2 = d2 + (float)cz * scale_fac + off + c2;

    float qr = f[3], qx = f[4], qy = f[5], qz = f[6];
    float qn = rsqrtf(qr*qr + qx*qx + qy*qy + qz*qz);
    qr *= qn; qx *= qn; qy *= qn; qz *= qn;

    float R00 = 1.0f - 2.0f*(qy*qy + qz*qz);
    float R01 = 2.0f*(qx*qy - qr*qz);
    float R02 = 2.0f*(qx*qz + qr*qy);
    float R10 = 2.0f*(qx*qy + qr*qz);
    float R11 = 1.0f - 2.0f*(qx*qx + qz*qz);
    float R12 = 2.0f*(qy*qz - qr*qx);
    float R20 = 2.0f*(qx*qz - qr*qy);
    float R21 = 2.0f*(qy*qz + qr*qx);
    float R22 = 1.0f - 2.0f*(qx*qx + qy*qy);

    float s0 = fsigmoid(f[7]) * scale_fac;
    float s1 = fsigmoid(f[8]) * scale_fac;
    float s2 = fsigmoid(f[9]) * scale_fac;
    float v0 = s0*s0, v1 = s1*s1, v2 = s2*s2;

    float c00 = R00*R00*v0 + R01*R01*v1 + R02*R02*v2;
    float c01 = R00*R10*v0 + R01*R11*v1 + R02*R12*v2;
    float c02 = R00*R20*v0 + R01*R21*v1 + R02*R22*v2;
    float c11 = R10*R10*v0 + R11*R11*v1 + R12*R12*v2;
    float c12 = R10*R20*v0 + R11*R21*v1 + R12*R22*v2;
    float c22 = R20*R20*v0 + R21*R21*v1 + R22*R22*v2;

    o0 = make_float4(m0,  m1,  m2,  c00);
    o1 = make_float4(c01, c02, c01, c11);
    o2 = make_float4(c12, c02, c12, c22);
    o3 = make_float4(fsigmoid(f[10]), fsigmoid(f[11]),
                     fsigmoid(f[12]), fsigmoid(f[13] - 4.0f));
}

__global__ void __launch_bounds__(512)
voxel_kernel(const float* __restrict__ ht,
             const float* __restrict__ cam,
             const float* __restrict__ far_p,
             const int*   __restrict__ vsz_p,
             float*       __restrict__ out)
{
    // pool: cnt[4096] (16 KB, sort phase) overlaid with float4 stage (40 KB)
    __shared__ __align__(16) unsigned char pool[16 * 32 * 5 * 16];  // 40960 B
    unsigned* cnt    = (unsigned*)pool;
    float4*   stage4 = (float4*)pool;
    __shared__ unsigned short perm[CAP];    // 5.5 KB
    __shared__ unsigned wsum[16];

    int b = blockIdx.x;
    unsigned start = g_base[b];
    unsigned end   = (b == NB - 1) ? NVOX : g_base[b + 1];
    int n  = (int)(end - start);
    int ns = n < CAP ? n : CAP;

    for (int k = threadIdx.x; k < SUBNB; k += 512) cnt[k] = 0u;
    __syncthreads();

    // load this thread's records once; reuse across hist + perm passes
    unsigned mybin[MYMAX];
    int nmy = 0;
    for (int j = threadIdx.x; j < ns; j += 512) {
        unsigned bin = hash_pc(g_records[start + j].y) & (SUBNB - 1);
        mybin[nmy++] = bin;
        atomicAdd(&cnt[bin], 1u);
    }
    __syncthreads();

    // exclusive scan of 4096 counters: 512 threads x 8 contiguous each
    int base_k = threadIdx.x * 8;
    unsigned loc[8], tsum = 0;
    #pragma unroll
    for (int q = 0; q < 8; q++) { loc[q] = cnt[base_k + q]; tsum += loc[q]; }
    unsigned incl = tsum;
    int lane = threadIdx.x & 31, wid = threadIdx.x >> 5;
    #pragma unroll
    for (int o = 1; o < 32; o <<= 1) {
        unsigned t = __shfl_up_sync(0xffffffffu, incl, o);
        if (lane >= o) incl += t;
    }
    if (lane == 31) wsum[wid] = incl;
    __syncthreads();
    if (threadIdx.x == 0) {
        unsigned run = 0;
        #pragma unroll
        for (int w = 0; w < 16; w++) { unsigned t = wsum[w]; wsum[w] = run; run += t; }
    }
    __syncthreads();
    unsigned run = wsum[wid] + incl - tsum;
    #pragma unroll
    for (int q = 0; q < 8; q++) { unsigned t = loc[q]; cnt[base_k + q] = run; run += t; }
    __syncthreads();

    // build sorted permutation from cached bins
    #pragma unroll
    for (int q = 0; q < MYMAX; q++) {
        if (q < nmy) {
            unsigned pos = atomicAdd(&cnt[mybin[q]], 1u);
            perm[pos] = (unsigned short)(threadIdx.x + (q << 9));
        }
    }
    __syncthreads();   // cnt dead from here; pool becomes stage4

    float far = __ldg(far_p);
    float vsz = vsz_p ? (float)__ldg(vsz_p) : 128.0f;
    float scale_fac = 2.0f * far / vsz;
    float c0 = __ldg(cam + 0), c1 = __ldg(cam + 1), c2 = __ldg(cam + 2);
    float mean = g_mean;
    float kfac = g_inv_std * scale_fac * (1.0f / 6.0f);

    // ---- process: compute -> float4 smem stage -> cooperative 4-lane stores ----
    float4* wst = stage4 + wid * (32 * 5);
    int rounds = (ns + 511) >> 9;
    for (int R = 0; R < rounds; R++) {
        int jb = (R << 9) + (wid << 5);
        if (jb >= ns) break;                  // uniform within warp
        int j  = jb + lane;
        int jc = j < ns ? j : ns - 1;
        uint2 r = g_records[start + (unsigned)perm[jc]];

        float4 o0, o1, o2, o3; unsigned i;
        compute_rec(r, ht, scale_fac, far, c0, c1, c2, mean, kfac,
                    o0, o1, o2, o3, i);

        float4* st = wst + lane * 5;
        st[0] = o0; st[1] = o1; st[2] = o2; st[3] = o3;
        __syncwarp();

        #pragma unroll
        for (int g = 0; g < 4; g++) {
            int rr = ((lane >> 2) << 2) + g;
            int qq = lane & 3;
            unsigned ii = __shfl_sync(0xffffffffu, i, rr);
            float4 v = wst[rr * 5 + qq];
            if (jb + rr < ns)
                __stcs((float4*)(out + (size_t)ii * 16) + qq, v);
        }
        __syncwarp();
    }

    // overflow records (bucket larger than CAP): direct stores (rare/none)
    for (int j = CAP + threadIdx.x; j < n; j += 512) {
        float4 o0, o1, o2, o3; unsigned i;
        compute_rec(g_records[start + j], ht, scale_fac, far, c0, c1, c2,
                    mean, kfac, o0, o1, o2, o3, i);
        float4* o = (float4*)(out + (size_t)i * 16);
        __stcs(o + 0, o0); __stcs(o + 1, o1);
        __stcs(o + 2, o2); __stcs(o + 3, o3);
    }
}

// ---------------- launcher ----------------
extern "C" void kernel_launch(void* const* d_in, const int* in_sizes, int n_in,
                              void* d_out, int out_size)
{
    const int*   coords = (const int*)  d_in[0];
    const float* ht     = (const float*)d_in[1];
    const float* cam    = (const float*)d_in[2];
    const float* far_p  = (const float*)d_in[3];
    const int*   vsz_p  = (n_in >= 5) ? (const int*)d_in[4] : nullptr;
    float* out = (float*)d_out;

    reduce_hist_kernel<<<RB + NBLK, 1024>>>((const float4*)ht, coords);
    offsets_kernel<<<1, NB>>>();
    scatter_kernel<<<NBLK, 1024>>>(coords);
    voxel_kernel<<<NB, 512>>>(ht, cam, far_p, vsz_p, out);
}

// round 14
// speedup vs baseline: 1.3117x; 1.3117x over previous
#include <cuda_runtime.h>
#include <math.h>

#define TABLE_SIZE 4194304          // 2^22
#define TABLE_MASK (TABLE_SIZE - 1)
#define NVOX (128*128*128)          // 2,097,152
#define NB 1024                     // global buckets (idx >> 12)
#define BSHIFT 12
#define NBLK 256                    // hist/scatter fat blocks
#define CHUNK (NVOX / NBLK)         // 8192
#define RB 512                      // reduce blocks inside fused kernel
#define SUBNB 4096                  // in-block sort bins (idx & 4095)
#define CAP 2816                    // max records locally sorted per bucket
#define MYMAX 6                     // ceil(CAP/512) records per thread

// ---------------- device-global scratch (allocation-free) ----------------
__device__ double   g_part_s[RB];
__device__ double   g_part_ss[RB];
__device__ float    g_mean;
__device__ float    g_inv_std;
__device__ unsigned g_bhist[NB * NBLK];   // 1 MB, BUCKET-MAJOR: [k*NBLK + b]
__device__ unsigned g_coltot[NB];         // per-bucket totals
__device__ unsigned g_base[NB];           // exclusive bucket bases
__device__ uint2    g_records[NVOX];      // (voxel_id, packed coords) 16 MB

__device__ __forceinline__ unsigned hash_idx(int cx, int cy, int cz) {
    unsigned h = (unsigned)cx ^ ((unsigned)cy * 2654435761u)
                             ^ ((unsigned)cz * 805459861u);
    return h & TABLE_MASK;
}
__device__ __forceinline__ unsigned hash_pc(unsigned pc) {
    return hash_idx((int)(pc & 127u), (int)((pc >> 7) & 127u),
                    (int)((pc >> 14) & 127u));
}

// ------- stage 1 (fused): table stats reduce + coord bucket histograms -------
__global__ void __launch_bounds__(1024)
reduce_hist_kernel(const float4* __restrict__ p, const int* __restrict__ coords)
{
    if (blockIdx.x < RB) {
        const int M4 = 3 * TABLE_SIZE / 4;
        double s = 0.0, ss = 0.0;
        int stride = RB * 1024;
        for (int i = blockIdx.x * 1024 + threadIdx.x; i < M4; i += stride) {
            float4 v = __ldcs(p + i);
            s  += (double)v.x + (double)v.y + (double)v.z + (double)v.w;
            ss += (double)v.x * v.x + (double)v.y * v.y
                + (double)v.z * v.z + (double)v.w * v.w;
        }
        #pragma unroll
        for (int o = 16; o > 0; o >>= 1) {
            s  += __shfl_down_sync(0xffffffffu, s,  o);
            ss += __shfl_down_sync(0xffffffffu, ss, o);
        }
        __shared__ double sh_s[32], sh_ss[32];
        int w = threadIdx.x >> 5, l = threadIdx.x & 31;
        if (l == 0) { sh_s[w] = s; sh_ss[w] = ss; }
        __syncthreads();
        if (threadIdx.x == 0) {
            double ts = 0.0, tss = 0.0;
            for (int k = 0; k < 32; k++) { ts += sh_s[k]; tss += sh_ss[k]; }
            g_part_s[blockIdx.x]  = ts;
            g_part_ss[blockIdx.x] = tss;
        }
    } else {
        __shared__ unsigned sh[NB];
        sh[threadIdx.x] = 0u;
        __syncthreads();
        int b = blockIdx.x - RB;
        int base = b * CHUNK;
        #pragma unroll 8
        for (int v = threadIdx.x; v < CHUNK; v += 1024) {
            int i = base + v;
            unsigned idx = hash_idx(coords[3*i], coords[3*i+1], coords[3*i+2]);
            atomicAdd(&sh[idx >> BSHIFT], 1u);
        }
        __syncthreads();
        // transposed (bucket-major) store
        g_bhist[(size_t)threadIdx.x * NBLK + b] = sh[threadIdx.x];
    }
}

// ---- stage 2a: per-bucket column scan (parallel, 1024 blocks) ----
__global__ void __launch_bounds__(NBLK)
offsets_a_kernel() {
    int k = blockIdx.x;          // bucket
    int t = threadIdx.x;         // block index within column
    unsigned v = g_bhist[(size_t)k * NBLK + t];   // coalesced
    int lane = t & 31, w = t >> 5;
    unsigned incl = v;
    #pragma unroll
    for (int o = 1; o < 32; o <<= 1) {
        unsigned x = __shfl_up_sync(0xffffffffu, incl, o);
        if (lane >= o) incl += x;
    }
    __shared__ unsigned ws[8];
    if (lane == 31) ws[w] = incl;
    __syncthreads();
    if (t == 0) {
        unsigned run = 0;
        #pragma unroll
        for (int q = 0; q < 8; q++) { unsigned x = ws[q]; ws[q] = run; run += x; }
    }
    __syncthreads();
    unsigned excl = ws[w] + incl - v;
    g_bhist[(size_t)k * NBLK + t] = excl;
    if (t == NBLK - 1) g_coltot[k] = excl + v;
}

// ---- stage 2b: stats finalize + top-level scan of bucket totals ----
__global__ void __launch_bounds__(NB)
offsets_b_kernel() {
    int k = threadIdx.x;
    {
        double s  = (k < RB) ? g_part_s[k]  : 0.0;
        double ss = (k < RB) ? g_part_ss[k] : 0.0;
        #pragma unroll
        for (int o = 16; o > 0; o >>= 1) {
            s  += __shfl_down_sync(0xffffffffu, s,  o);
            ss += __shfl_down_sync(0xffffffffu, ss, o);
        }
        __shared__ double sh_s[32], sh_ss[32];
        int w = k >> 5, l = k & 31;
        if (l == 0) { sh_s[w] = s; sh_ss[w] = ss; }
        __syncthreads();
        if (k == 0) {
            double ts = 0.0, tss = 0.0;
            for (int q = 0; q < 32; q++) { ts += sh_s[q]; tss += sh_ss[q]; }
            const double M = 3.0 * (double)TABLE_SIZE;
            double mean = ts / M;
            double var  = (tss - ts * ts / M) / (M - 1.0);
            g_mean    = (float)mean;
            g_inv_std = (float)(1.0 / sqrt(var));
        }
        __syncthreads();
    }
    unsigned own = g_coltot[k];
    __shared__ unsigned s[NB];
    s[k] = own;
    __syncthreads();
    for (int off = 1; off < NB; off <<= 1) {
        unsigned v = (k >= off) ? s[k - off] : 0u;
        __syncthreads();
        s[k] += v;
        __syncthreads();
    }
    g_base[k] = s[k] - own;
}

// ------- stage 3: scatter v3 — smem counting-sort, near-coalesced writes -------
// dynamic smem: cur[NB] + lbase[NB] + lcnt[NB] (12 KB) + srec[CHUNK] (64 KB)
__global__ void __launch_bounds__(1024)
scatter_kernel(const int* __restrict__ coords) {
    extern __shared__ unsigned dsm[];
    unsigned* cur   = dsm;
    unsigned* lbase = dsm + NB;
    unsigned* lcnt  = dsm + 2 * NB;
    uint2*    srec  = (uint2*)(dsm + 3 * NB);

    int b = blockIdx.x;
    int k = threadIdx.x;
    cur[k]  = g_base[k] + g_bhist[(size_t)k * NBLK + b];
    lcnt[k] = 0u;
    __syncthreads();

    int base = b * CHUNK;
    unsigned my_i[8], my_pc[8], my_bk[8];
    #pragma unroll
    for (int q = 0; q < 8; q++) {
        int i = base + k + (q << 10);
        int cx = __ldcs(coords + 3*i + 0);
        int cy = __ldcs(coords + 3*i + 1);
        int cz = __ldcs(coords + 3*i + 2);
        unsigned idx = hash_idx(cx, cy, cz);
        my_i[q]  = (unsigned)i;
        my_pc[q] = (unsigned)cx | ((unsigned)cy << 7) | ((unsigned)cz << 14);
        my_bk[q] = idx >> BSHIFT;
        atomicAdd(&lcnt[my_bk[q]], 1u);
    }
    __syncthreads();

    // exclusive scan of lcnt (1024 bins) via Hillis-Steele in lbase
    unsigned own = lcnt[k];
    lbase[k] = own;
    __syncthreads();
    for (int off = 1; off < NB; off <<= 1) {
        unsigned v = (k >= off) ? lbase[k - off] : 0u;
        __syncthreads();
        lbase[k] += v;
        __syncthreads();
    }
    unsigned excl = lbase[k] - own;
    __syncthreads();
    lbase[k] = excl;
    lcnt[k]  = excl;
    __syncthreads();

    // local scatter into bucket-sorted smem order
    #pragma unroll
    for (int q = 0; q < 8; q++) {
        unsigned pos = atomicAdd(&lcnt[my_bk[q]], 1u);
        srec[pos] = make_uint2(my_i[q], my_pc[q]);
    }
    __syncthreads();

    // write out in sorted order: bucket runs -> consecutive destinations
    #pragma unroll
    for (int q = 0; q < 8; q++) {
        int p = k + (q << 10);
        uint2 r = srec[p];
        unsigned bk = hash_pc(r.y) >> BSHIFT;
        unsigned dest = cur[bk] + ((unsigned)p - lbase[bk]);
        g_records[dest] = r;
    }
}

// ---------------- stage 4: per-bucket local sort (perm) + process (R10) ---------
__device__ __forceinline__ float fsigmoid(float x) {
    return 1.0f / (1.0f + __expf(-x));
}

__device__ __forceinline__ void
compute_rec(uint2 r, const float* __restrict__ ht,
            float scale_fac, float far, float c0, float c1, float c2,
            float mean, float kfac,
            float4& o0, float4& o1, float4& o2, float4& o3, unsigned& iout)
{
    iout = r.x;
    unsigned pc = r.y;
    unsigned idx = hash_pc(pc);

    float f[14];
    #pragma unroll
    for (int q = 0; q < 14; q++)
        f[q] = __ldg(ht + (size_t)q * TABLE_SIZE + idx);

    int cx = (int)( pc        & 127u);
    int cy = (int)((pc >> 7)  & 127u);
    int cz = (int)((pc >> 14) & 127u);

    float d0 = (f[0] - mean) * kfac;
    float d1 = (f[1] - mean) * kfac;
    float d2 = (f[2] - mean) * kfac;

    float off = 0.5f * scale_fac - far;
    float m0 = d0 + (float)cx * scale_fac + off + c0;
    float m1 = d1 + (float)cy * scale_fac + off + c1;
    float m2 = d2 + (float)cz * scale_fac + off + c2;

    float qr = f[3], qx = f[4], qy = f[5], qz = f[6];
    float qn = rsqrtf(qr*qr + qx*qx + qy*qy + qz*qz);
    qr *= qn; qx *= qn; qy *= qn; qz *= qn;

    float R00 = 1.0f - 2.0f*(qy*qy + qz*qz);
    float R01 = 2.0f*(qx*qy - qr*qz);
    float R02 = 2.0f*(qx*qz + qr*qy);
    float R10 = 2.0f*(qx*qy + qr*qz);
    float R11 = 1.0f - 2.0f*(qx*qx + qz*qz);
    float R12 = 2.0f*(qy*qz - qr*qx);
    float R20 = 2.0f*(qx*qz - qr*qy);
    float R21 = 2.0f*(qy*qz + qr*qx);
    float R22 = 1.0f - 2.0f*(qx*qx + qy*qy);

    float s0 = fsigmoid(f[7]) * scale_fac;
    float s1 = fsigmoid(f[8]) * scale_fac;
    float s2 = fsigmoid(f[9]) * scale_fac;
    float v0 = s0*s0, v1 = s1*s1, v2 = s2*s2;

    float c00 = R00*R00*v0 + R01*R01*v1 + R02*R02*v2;
    float c01 = R00*R10*v0 + R01*R11*v1 + R02*R12*v2;
    float c02 = R00*R20*v0 + R01*R21*v1 + R02*R22*v2;
    float c11 = R10*R10*v0 + R11*R11*v1 + R12*R12*v2;
    float c12 = R10*R20*v0 + R11*R21*v1 + R12*R22*v2;
    float c22 = R20*R20*v0 + R21*R21*v1 + R22*R22*v2;

    o0 = make_float4(m0,  m1,  m2,  c00);
    o1 = make_float4(c01, c02, c01, c11);
    o2 = make_float4(c12, c02, c12, c22);
    o3 = make_float4(fsigmoid(f[10]), fsigmoid(f[11]),
                     fsigmoid(f[12]), fsigmoid(f[13] - 4.0f));
}

__global__ void __launch_bounds__(512)
voxel_kernel(const float* __restrict__ ht,
             const float* __restrict__ cam,
             const float* __restrict__ far_p,
             const int*   __restrict__ vsz_p,
             float*       __restrict__ out)
{
    // pool: cnt[4096] (16 KB, sort phase) overlaid with float4 stage (40 KB)
    __shared__ __align__(16) unsigned char pool[16 * 32 * 5 * 16];  // 40960 B
    unsigned* cnt    = (unsigned*)pool;
    float4*   stage4 = (float4*)pool;
    __shared__ unsigned short perm[CAP];    // 5.5 KB
    __shared__ unsigned wsum[16];

    int b = blockIdx.x;
    unsigned start = g_base[b];
    unsigned end   = (b == NB - 1) ? NVOX : g_base[b + 1];
    int n  = (int)(end - start);
    int ns = n < CAP ? n : CAP;

    for (int k = threadIdx.x; k < SUBNB; k += 512) cnt[k] = 0u;
    __syncthreads();

    // load this thread's records once; reuse across hist + perm passes
    unsigned mybin[MYMAX];
    int nmy = 0;
    for (int j = threadIdx.x; j < ns; j += 512) {
        unsigned bin = hash_pc(g_records[start + j].y) & (SUBNB - 1);
        mybin[nmy++] = bin;
        atomicAdd(&cnt[bin], 1u);
    }
    __syncthreads();

    // exclusive scan of 4096 counters: 512 threads x 8 contiguous each
    int base_k = threadIdx.x * 8;
    unsigned loc[8], tsum = 0;
    #pragma unroll
    for (int q = 0; q < 8; q++) { loc[q] = cnt[base_k + q]; tsum += loc[q]; }
    unsigned incl = tsum;
    int lane = threadIdx.x & 31, wid = threadIdx.x >> 5;
    #pragma unroll
    for (int o = 1; o < 32; o <<= 1) {
        unsigned t = __shfl_up_sync(0xffffffffu, incl, o);
        if (lane >= o) incl += t;
    }
    if (lane == 31) wsum[wid] = incl;
    __syncthreads();
    if (threadIdx.x == 0) {
        unsigned run = 0;
        #pragma unroll
        for (int w = 0; w < 16; w++) { unsigned t = wsum[w]; wsum[w] = run; run += t; }
    }
    __syncthreads();
    unsigned run = wsum[wid] + incl - tsum;
    #pragma unroll
    for (int q = 0; q < 8; q++) { unsigned t = loc[q]; cnt[base_k + q] = run; run += t; }
    __syncthreads();

    // build sorted permutation from cached bins
    #pragma unroll
    for (int q = 0; q < MYMAX; q++) {
        if (q < nmy) {
            unsigned pos = atomicAdd(&cnt[mybin[q]], 1u);
            perm[pos] = (unsigned short)(threadIdx.x + (q << 9));
        }
    }
    __syncthreads();   // cnt dead from here; pool becomes stage4

    float far = __ldg(far_p);
    float vsz = vsz_p ? (float)__ldg(vsz_p) : 128.0f;
    float scale_fac = 2.0f * far / vsz;
    float c0 = __ldg(cam + 0), c1 = __ldg(cam + 1), c2 = __ldg(cam + 2);
    float mean = g_mean;
    float kfac = g_inv_std * scale_fac * (1.0f / 6.0f);

    // ---- process: compute -> float4 smem stage -> cooperative 4-lane stores ----
    float4* wst = stage4 + wid * (32 * 5);
    int rounds = (ns + 511) >> 9;
    for (int R = 0; R < rounds; R++) {
        int jb = (R << 9) + (wid << 5);
        if (jb >= ns) break;                  // uniform within warp
        int j  = jb + lane;
        int jc = j < ns ? j : ns - 1;
        uint2 r = g_records[start + (unsigned)perm[jc]];

        float4 o0, o1, o2, o3; unsigned i;
        compute_rec(r, ht, scale_fac, far, c0, c1, c2, mean, kfac,
                    o0, o1, o2, o3, i);

        float4* st = wst + lane * 5;
        st[0] = o0; st[1] = o1; st[2] = o2; st[3] = o3;
        __syncwarp();

        #pragma unroll
        for (int g = 0; g < 4; g++) {
            int rr = ((lane >> 2) << 2) + g;
            int qq = lane & 3;
            unsigned ii = __shfl_sync(0xffffffffu, i, rr);
            float4 v = wst[rr * 5 + qq];
            if (jb + rr < ns)
                __stcs((float4*)(out + (size_t)ii * 16) + qq, v);
        }
        __syncwarp();
    }

    // overflow records (bucket larger than CAP): direct stores (rare/none)
    for (int j = CAP + threadIdx.x; j < n; j += 512) {
        float4 o0, o1, o2, o3; unsigned i;
        compute_rec(g_records[start + j], ht, scale_fac, far, c0, c1, c2,
                    mean, kfac, o0, o1, o2, o3, i);
        float4* o = (float4*)(out + (size_t)i * 16);
        __stcs(o + 0, o0); __stcs(o + 1, o1);
        __stcs(o + 2, o2); __stcs(o + 3, o3);
    }
}

// ---------------- launcher ----------------
extern "C" void kernel_launch(void* const* d_in, const int* in_sizes, int n_in,
                              void* d_out, int out_size)
{
    const int*   coords = (const int*)  d_in[0];
    const float* ht     = (const float*)d_in[1];
    const float* cam    = (const float*)d_in[2];
    const float* far_p  = (const float*)d_in[3];
    const int*   vsz_p  = (n_in >= 5) ? (const int*)d_in[4] : nullptr;
    float* out = (float*)d_out;

    const int scatter_smem = 3 * NB * 4 + CHUNK * 8;   // 12 KB + 64 KB = 77824 B
    static int configured = 0;
    if (!configured) {
        cudaFuncSetAttribute(scatter_kernel,
                             cudaFuncAttributeMaxDynamicSharedMemorySize,
                             scatter_smem);
        configured = 1;
    }

    reduce_hist_kernel<<<RB + NBLK, 1024>>>((const float4*)ht, coords);
    offsets_a_kernel<<<NB, NBLK>>>();
    offsets_b_kernel<<<1, NB>>>();
    scatter_kernel<<<NBLK, 1024, scatter_smem>>>(coords);
    voxel_kernel<<<NB, 512>>>(ht, cam, far_p, vsz_p, out);
}

// round 15
// speedup vs baseline: 1.3563x; 1.0340x over previous
#include <cuda_runtime.h>
#include <math.h>

#define TABLE_SIZE 4194304          // 2^22
#define TABLE_MASK (TABLE_SIZE - 1)
#define NVOX (128*128*128)          // 2,097,152
#define NB 1024                     // global buckets (idx >> 12)
#define BSHIFT 12
#define NBLK 256                    // hist/scatter fat blocks
#define CHUNK (NVOX / NBLK)         // 8192
#define RB 512                      // reduce blocks inside fused kernel
#define SUBNB 4096                  // in-block sort bins (idx & 4095)
#define CAP 2816                    // max records locally sorted per bucket
#define MYMAX 6                     // ceil(CAP/512) records per thread

// ---------------- device-global scratch (allocation-free) ----------------
__device__ double   g_part_s[RB];
__device__ double   g_part_ss[RB];
__device__ float    g_mean;
__device__ float    g_inv_std;
__device__ unsigned g_bhist[NB * NBLK];   // 1 MB, BUCKET-MAJOR: [k*NBLK + b]
__device__ unsigned g_coltot[NB];         // per-bucket totals
__device__ unsigned g_base[NB];           // exclusive bucket bases (for voxel)
__device__ uint2    g_records[NVOX];      // (voxel_id, packed coords) 16 MB

__device__ __forceinline__ unsigned hash_idx(int cx, int cy, int cz) {
    unsigned h = (unsigned)cx ^ ((unsigned)cy * 2654435761u)
                             ^ ((unsigned)cz * 805459861u);
    return h & TABLE_MASK;
}
__device__ __forceinline__ unsigned hash_pc(unsigned pc) {
    return hash_idx((int)(pc & 127u), (int)((pc >> 7) & 127u),
                    (int)((pc >> 14) & 127u));
}

// warp-shuffle block exclusive scan over 1024 values (one per thread)
__device__ __forceinline__ unsigned
block_excl_scan_1024(unsigned own, unsigned* tmp, int k) {
    int lane = k & 31, w = k >> 5;
    unsigned incl = own;
    #pragma unroll
    for (int o = 1; o < 32; o <<= 1) {
        unsigned x = __shfl_up_sync(0xffffffffu, incl, o);
        if (lane >= o) incl += x;
    }
    if (lane == 31) tmp[w] = incl;
    __syncthreads();
    if (w == 0) {
        unsigned v = tmp[lane];
        unsigned vi = v;
        #pragma unroll
        for (int o = 1; o < 32; o <<= 1) {
            unsigned x = __shfl_up_sync(0xffffffffu, vi, o);
            if (lane >= o) vi += x;
        }
        tmp[lane] = vi - v;          // exclusive warp offsets
    }
    __syncthreads();
    return tmp[w] + incl - own;
}

// ------- stage 1 (fused): table stats reduce + coord bucket histograms -------
__global__ void __launch_bounds__(1024)
reduce_hist_kernel(const float4* __restrict__ p, const int* __restrict__ coords)
{
    if (blockIdx.x < RB) {
        const int M4 = 3 * TABLE_SIZE / 4;
        double s = 0.0, ss = 0.0;
        int stride = RB * 1024;
        for (int i = blockIdx.x * 1024 + threadIdx.x; i < M4; i += stride) {
            float4 v = __ldcs(p + i);
            s  += (double)v.x + (double)v.y + (double)v.z + (double)v.w;
            ss += (double)v.x * v.x + (double)v.y * v.y
                + (double)v.z * v.z + (double)v.w * v.w;
        }
        #pragma unroll
        for (int o = 16; o > 0; o >>= 1) {
            s  += __shfl_down_sync(0xffffffffu, s,  o);
            ss += __shfl_down_sync(0xffffffffu, ss, o);
        }
        __shared__ double sh_s[32], sh_ss[32];
        int w = threadIdx.x >> 5, l = threadIdx.x & 31;
        if (l == 0) { sh_s[w] = s; sh_ss[w] = ss; }
        __syncthreads();
        if (threadIdx.x == 0) {
            double ts = 0.0, tss = 0.0;
            for (int k = 0; k < 32; k++) { ts += sh_s[k]; tss += sh_ss[k]; }
            g_part_s[blockIdx.x]  = ts;
            g_part_ss[blockIdx.x] = tss;
        }
    } else {
        __shared__ unsigned sh[NB];
        sh[threadIdx.x] = 0u;
        __syncthreads();
        int b = blockIdx.x - RB;
        int base = b * CHUNK;
        #pragma unroll 8
        for (int v = threadIdx.x; v < CHUNK; v += 1024) {
            int i = base + v;
            unsigned idx = hash_idx(coords[3*i], coords[3*i+1], coords[3*i+2]);
            atomicAdd(&sh[idx >> BSHIFT], 1u);
        }
        __syncthreads();
        // transposed (bucket-major) store
        g_bhist[(size_t)threadIdx.x * NBLK + b] = sh[threadIdx.x];
    }
}

// ---- stage 2: per-bucket column scan (1024 blocks) + stats finalize (block NB) ----
__global__ void __launch_bounds__(NBLK)
offsets_a_kernel() {
    if (blockIdx.x == NB) {
        // stats finalize from reduce partials
        int t = threadIdx.x;
        double s  = g_part_s[t]  + g_part_s[t + 256];
        double ss = g_part_ss[t] + g_part_ss[t + 256];
        #pragma unroll
        for (int o = 16; o > 0; o >>= 1) {
            s  += __shfl_down_sync(0xffffffffu, s,  o);
            ss += __shfl_down_sync(0xffffffffu, ss, o);
        }
        __shared__ double sh_s[8], sh_ss[8];
        int w = t >> 5, l = t & 31;
        if (l == 0) { sh_s[w] = s; sh_ss[w] = ss; }
        __syncthreads();
        if (t == 0) {
            double ts = 0.0, tss = 0.0;
            for (int q = 0; q < 8; q++) { ts += sh_s[q]; tss += sh_ss[q]; }
            const double M = 3.0 * (double)TABLE_SIZE;
            double mean = ts / M;
            double var  = (tss - ts * ts / M) / (M - 1.0);
            g_mean    = (float)mean;
            g_inv_std = (float)(1.0 / sqrt(var));
        }
        return;
    }
    int k = blockIdx.x;          // bucket
    int t = threadIdx.x;         // block index within column
    unsigned v = g_bhist[(size_t)k * NBLK + t];   // coalesced
    int lane = t & 31, w = t >> 5;
    unsigned incl = v;
    #pragma unroll
    for (int o = 1; o < 32; o <<= 1) {
        unsigned x = __shfl_up_sync(0xffffffffu, incl, o);
        if (lane >= o) incl += x;
    }
    __shared__ unsigned ws[8];
    if (lane == 31) ws[w] = incl;
    __syncthreads();
    if (t == 0) {
        unsigned run = 0;
        #pragma unroll
        for (int q = 0; q < 8; q++) { unsigned x = ws[q]; ws[q] = run; run += x; }
    }
    __syncthreads();
    unsigned excl = ws[w] + incl - v;
    g_bhist[(size_t)k * NBLK + t] = excl;
    if (t == NBLK - 1) g_coltot[k] = excl + v;
}

// ------- stage 3: scatter v4 — inline base scan + shuffle scans + sorted writes -------
// dynamic smem: cur[NB] + lbase[NB] + lcnt[NB] + tmp[32] (12.1 KB) + srec[CHUNK] (64 KB)
__global__ void __launch_bounds__(1024)
scatter_kernel(const int* __restrict__ coords) {
    extern __shared__ unsigned dsm[];
    unsigned* cur   = dsm;                 // 1024
    unsigned* lbase = dsm + NB;            // 1024
    unsigned* lcnt  = dsm + 2 * NB;        // 1024
    unsigned* tmp   = dsm + 3 * NB;        // 32
    uint2*    srec  = (uint2*)(dsm + 3 * NB + 32);   // 8192 uint2 (8B aligned)

    int b = blockIdx.x;
    int k = threadIdx.x;

    // inline global bucket bases: exclusive scan of coltot (redundant per block, cheap)
    unsigned ct = g_coltot[k];
    unsigned gbase = block_excl_scan_1024(ct, tmp, k);
    cur[k]  = gbase + g_bhist[(size_t)k * NBLK + b];
    lcnt[k] = 0u;
    if (b == 0) g_base[k] = gbase;     // publish for voxel kernel
    __syncthreads();

    int base = b * CHUNK;
    unsigned my_i[8], my_pc[8], my_bk[8];
    #pragma unroll
    for (int q = 0; q < 8; q++) {
        int i = base + k + (q << 10);
        int cx = __ldcs(coords + 3*i + 0);
        int cy = __ldcs(coords + 3*i + 1);
        int cz = __ldcs(coords + 3*i + 2);
        unsigned idx = hash_idx(cx, cy, cz);
        my_i[q]  = (unsigned)i;
        my_pc[q] = (unsigned)cx | ((unsigned)cy << 7) | ((unsigned)cz << 14);
        my_bk[q] = idx >> BSHIFT;
        atomicAdd(&lcnt[my_bk[q]], 1u);
    }
    __syncthreads();

    // exclusive scan of local counts (shuffle-based)
    unsigned own  = lcnt[k];
    unsigned excl = block_excl_scan_1024(own, tmp, k);
    lbase[k] = excl;
    lcnt[k]  = excl;
    __syncthreads();

    // local scatter into bucket-sorted smem order (carry bk in pc bits 21..30)
    #pragma unroll
    for (int q = 0; q < 8; q++) {
        unsigned pos = atomicAdd(&lcnt[my_bk[q]], 1u);
        srec[pos] = make_uint2(my_i[q], my_pc[q] | (my_bk[q] << 21));
    }
    __syncthreads();

    // write out in sorted order: bucket runs -> consecutive destinations
    #pragma unroll
    for (int q = 0; q < 8; q++) {
        int p = k + (q << 10);
        uint2 r = srec[p];
        unsigned bk = r.y >> 21;
        unsigned dest = cur[bk] + ((unsigned)p - lbase[bk]);
        g_records[dest] = make_uint2(r.x, r.y & 0x1FFFFFu);
    }
}

// ---------------- stage 4: per-bucket local sort (perm) + process (R10) ---------
__device__ __forceinline__ float fsigmoid(float x) {
    return 1.0f / (1.0f + __expf(-x));
}

__device__ __forceinline__ void
compute_rec(uint2 r, const float* __restrict__ ht,
            float scale_fac, float far, float c0, float c1, float c2,
            float mean, float kfac,
            float4& o0, float4& o1, float4& o2, float4& o3, unsigned& iout)
{
    iout = r.x;
    unsigned pc = r.y;
    unsigned idx = hash_pc(pc);

    float f[14];
    #pragma unroll
    for (int q = 0; q < 14; q++)
        f[q] = __ldg(ht + (size_t)q * TABLE_SIZE + idx);

    int cx = (int)( pc        & 127u);
    int cy = (int)((pc >> 7)  & 127u);
    int cz = (int)((pc >> 14) & 127u);

    float d0 = (f[0] - mean) * kfac;
    float d1 = (f[1] - mean) * kfac;
    float d2 = (f[2] - mean) * kfac;

    float off = 0.5f * scale_fac - far;
    float m0 = d0 + (float)cx * scale_fac + off + c0;
    float m1 = d1 + (float)cy * scale_fac + off + c1;
    float m2 = d2 + (float)cz * scale_fac + off + c2;

    float qr = f[3], qx = f[4], qy = f[5], qz = f[6];
    float qn = rsqrtf(qr*qr + qx*qx + qy*qy + qz*qz);
    qr *= qn; qx *= qn; qy *= qn; qz *= qn;

    float R00 = 1.0f - 2.0f*(qy*qy + qz*qz);
    float R01 = 2.0f*(qx*qy - qr*qz);
    float R02 = 2.0f*(qx*qz + qr*qy);
    float R10 = 2.0f*(qx*qy + qr*qz);
    float R11 = 1.0f - 2.0f*(qx*qx + qz*qz);
    float R12 = 2.0f*(qy*qz - qr*qx);
    float R20 = 2.0f*(qx*qz - qr*qy);
    float R21 = 2.0f*(qy*qz + qr*qx);
    float R22 = 1.0f - 2.0f*(qx*qx + qy*qy);

    float s0 = fsigmoid(f[7]) * scale_fac;
    float s1 = fsigmoid(f[8]) * scale_fac;
    float s2 = fsigmoid(f[9]) * scale_fac;
    float v0 = s0*s0, v1 = s1*s1, v2 = s2*s2;

    float c00 = R00*R00*v0 + R01*R01*v1 + R02*R02*v2;
    float c01 = R00*R10*v0 + R01*R11*v1 + R02*R12*v2;
    float c02 = R00*R20*v0 + R01*R21*v1 + R02*R22*v2;
    float c11 = R10*R10*v0 + R11*R11*v1 + R12*R12*v2;
    float c12 = R10*R20*v0 + R11*R21*v1 + R12*R22*v2;
    float c22 = R20*R20*v0 + R21*R21*v1 + R22*R22*v2;

    o0 = make_float4(m0,  m1,  m2,  c00);
    o1 = make_float4(c01, c02, c01, c11);
    o2 = make_float4(c12, c02, c12, c22);
    o3 = make_float4(fsigmoid(f[10]), fsigmoid(f[11]),
                     fsigmoid(f[12]), fsigmoid(f[13] - 4.0f));
}

__global__ void __launch_bounds__(512)
voxel_kernel(const float* __restrict__ ht,
             const float* __restrict__ cam,
             const float* __restrict__ far_p,
             const int*   __restrict__ vsz_p,
             float*       __restrict__ out)
{
    // pool: cnt[4096] (16 KB, sort phase) overlaid with float4 stage (40 KB)
    __shared__ __align__(16) unsigned char pool[16 * 32 * 5 * 16];  // 40960 B
    unsigned* cnt    = (unsigned*)pool;
    float4*   stage4 = (float4*)pool;
    __shared__ unsigned short perm[CAP];    // 5.5 KB
    __shared__ unsigned wsum[16];

    int b = blockIdx.x;
    unsigned start = g_base[b];
    unsigned end   = (b == NB - 1) ? NVOX : g_base[b + 1];
    int n  = (int)(end - start);
    int ns = n < CAP ? n : CAP;

    for (int k = threadIdx.x; k < SUBNB; k += 512) cnt[k] = 0u;
    __syncthreads();

    // load this thread's records once; reuse across hist + perm passes
    unsigned mybin[MYMAX];
    int nmy = 0;
    for (int j = threadIdx.x; j < ns; j += 512) {
        unsigned bin = hash_pc(g_records[start + j].y) & (SUBNB - 1);
        mybin[nmy++] = bin;
        atomicAdd(&cnt[bin], 1u);
    }
    __syncthreads();

    // exclusive scan of 4096 counters: 512 threads x 8 contiguous each
    int base_k = threadIdx.x * 8;
    unsigned loc[8], tsum = 0;
    #pragma unroll
    for (int q = 0; q < 8; q++) { loc[q] = cnt[base_k + q]; tsum += loc[q]; }
    unsigned incl = tsum;
    int lane = threadIdx.x & 31, wid = threadIdx.x >> 5;
    #pragma unroll
    for (int o = 1; o < 32; o <<= 1) {
        unsigned t = __shfl_up_sync(0xffffffffu, incl, o);
        if (lane >= o) incl += t;
    }
    if (lane == 31) wsum[wid] = incl;
    __syncthreads();
    if (threadIdx.x == 0) {
        unsigned run = 0;
        #pragma unroll
        for (int w = 0; w < 16; w++) { unsigned t = wsum[w]; wsum[w] = run; run += t; }
    }
    __syncthreads();
    unsigned run = wsum[wid] + incl - tsum;
    #pragma unroll
    for (int q = 0; q < 8; q++) { unsigned t = loc[q]; cnt[base_k + q] = run; run += t; }
    __syncthreads();

    // build sorted permutation from cached bins
    #pragma unroll
    for (int q = 0; q < MYMAX; q++) {
        if (q < nmy) {
            unsigned pos = atomicAdd(&cnt[mybin[q]], 1u);
            perm[pos] = (unsigned short)(threadIdx.x + (q << 9));
        }
    }
    __syncthreads();   // cnt dead from here; pool becomes stage4

    float far = __ldg(far_p);
    float vsz = vsz_p ? (float)__ldg(vsz_p) : 128.0f;
    float scale_fac = 2.0f * far / vsz;
    float c0 = __ldg(cam + 0), c1 = __ldg(cam + 1), c2 = __ldg(cam + 2);
    float mean = g_mean;
    float kfac = g_inv_std * scale_fac * (1.0f / 6.0f);

    // ---- process: compute -> float4 smem stage -> cooperative 4-lane stores ----
    float4* wst = stage4 + wid * (32 * 5);
    int rounds = (ns + 511) >> 9;
    for (int R = 0; R < rounds; R++) {
        int jb = (R << 9) + (wid << 5);
        if (jb >= ns) break;                  // uniform within warp
        int j  = jb + lane;
        int jc = j < ns ? j : ns - 1;
        uint2 r = g_records[start + (unsigned)perm[jc]];

        float4 o0, o1, o2, o3; unsigned i;
        compute_rec(r, ht, scale_fac, far, c0, c1, c2, mean, kfac,
                    o0, o1, o2, o3, i);

        float4* st = wst + lane * 5;
        st[0] = o0; st[1] = o1; st[2] = o2; st[3] = o3;
        __syncwarp();

        #pragma unroll
        for (int g = 0; g < 4; g++) {
            int rr = ((lane >> 2) << 2) + g;
            int qq = lane & 3;
            unsigned ii = __shfl_sync(0xffffffffu, i, rr);
            float4 v = wst[rr * 5 + qq];
            if (jb + rr < ns)
                __stcs((float4*)(out + (size_t)ii * 16) + qq, v);
        }
        __syncwarp();
    }

    // overflow records (bucket larger than CAP): direct stores (rare/none)
    for (int j = CAP + threadIdx.x; j < n; j += 512) {
        float4 o0, o1, o2, o3; unsigned i;
        compute_rec(g_records[start + j], ht, scale_fac, far, c0, c1, c2,
                    mean, kfac, o0, o1, o2, o3, i);
        float4* o = (float4*)(out + (size_t)i * 16);
        __stcs(o + 0, o0); __stcs(o + 1, o1);
        __stcs(o + 2, o2); __stcs(o + 3, o3);
    }
}

// ---------------- launcher ----------------
extern "C" void kernel_launch(void* const* d_in, const int* in_sizes, int n_in,
                              void* d_out, int out_size)
{
    const int*   coords = (const int*)  d_in[0];
    const float* ht     = (const float*)d_in[1];
    const float* cam    = (const float*)d_in[2];
    const float* far_p  = (const float*)d_in[3];
    const int*   vsz_p  = (n_in >= 5) ? (const int*)d_in[4] : nullptr;
    float* out = (float*)d_out;

    const int scatter_smem = (3 * NB + 32) * 4 + CHUNK * 8;   // 77952 B
    static int configured = 0;
    if (!configured) {
        cudaFuncSetAttribute(scatter_kernel,
                             cudaFuncAttributeMaxDynamicSharedMemorySize,
                             scatter_smem);
        configured = 1;
    }

    reduce_hist_kernel<<<RB + NBLK, 1024>>>((const float4*)ht, coords);
    offsets_a_kernel<<<NB + 1, NBLK>>>();
    scatter_kernel<<<NBLK, 1024, scatter_smem>>>(coords);
    voxel_kernel<<<NB, 512>>>(ht, cam, far_p, vsz_p, out);
}